// round 1
// baseline (speedup 1.0000x reference)
#include <cuda_runtime.h>
#include <stdint.h>

// MessageFunction: per-edge MLP (16 -> 64 -> 256) -> reshape [16,16] -> matvec
// with h_w -> segment_sum over index_v into out [n_node, 16].
//
// Fused thread-per-edge kernel. Weights live in dynamic shared memory
// (broadcast LDS, conflict-free). Inner products use packed fma.rn.f32x2
// (sm_103a FFMA2) to double fp32 FMA throughput.

#define NDIM 16
#define HID  64
#define TPB  256

// ---------------- f32x2 packed helpers ----------------
__device__ __forceinline__ unsigned long long ffma2(unsigned long long a,
                                                    unsigned long long b,
                                                    unsigned long long c) {
    unsigned long long d;
    asm("fma.rn.f32x2 %0, %1, %2, %3;" : "=l"(d) : "l"(a), "l"(b), "l"(c));
    return d;
}
__device__ __forceinline__ unsigned long long fadd2(unsigned long long a,
                                                    unsigned long long b) {
    unsigned long long d;
    asm("add.rn.f32x2 %0, %1, %2;" : "=l"(d) : "l"(a), "l"(b));
    return d;
}
__device__ __forceinline__ float lo32(unsigned long long v) {
    return __uint_as_float((unsigned)v);
}
__device__ __forceinline__ float hi32(unsigned long long v) {
    return __uint_as_float((unsigned)(v >> 32));
}
__device__ __forceinline__ unsigned long long dup2(float x) {
    unsigned u = __float_as_uint(x);
    return ((unsigned long long)u << 32) | (unsigned long long)u;
}

// ---------------- kernels ----------------
__global__ void zero_out_kernel(float* out, int n) {
    int i = blockIdx.x * blockDim.x + threadIdx.x;
    if (i < n) out[i] = 0.0f;
}

// Dynamic shared layout (floats):
//   [0, 1024)        sW1T  [HID][NDIM]   (W1 transposed: [j][k])
//   [1024, 1088)     sb1   [HID]
//   [1088, 17472)    sW2   [HID][256]    (row-major, row j = 256 floats)
//   [17472, 17728)   sb2   [256]
#define SMEM_FLOATS 17728

extern "C" __global__ void __launch_bounds__(TPB)
msg_kernel(const int* __restrict__ index_v,
           const float* __restrict__ h_w,
           const float* __restrict__ e_vw,
           const float* __restrict__ W1,
           const float* __restrict__ b1,
           const float* __restrict__ W2,
           const float* __restrict__ b2,
           float* __restrict__ out,
           int n_edge) {
    extern __shared__ float smem[];
    float* sW1T = smem;            // [HID][NDIM]
    float* sb1  = smem + 1024;     // [HID]
    float* sW2  = smem + 1088;     // [HID][256]
    float* sb2  = smem + 17472;    // [256]

    const int tid = threadIdx.x;

    // Stage weights in shared. W1 arrives [k=16][j=64]; store transposed [j][k].
    for (int i = tid; i < NDIM * HID; i += TPB) {
        int k = i >> 6;     // row in W1
        int j = i & 63;     // col in W1
        sW1T[j * NDIM + k] = W1[i];
    }
    if (tid < HID) sb1[tid] = b1[tid];
    for (int i = tid; i < HID * 256; i += TPB) sW2[i] = W2[i];
    if (tid < 256) sb2[tid] = b2[tid];
    __syncthreads();

    const int e = blockIdx.x * TPB + tid;
    if (e >= n_edge) return;

    // Load this edge's h_w and e_vw rows as packed f32x2 pairs.
    unsigned long long hw2[8], ev2[8];
    {
        const uint4* ph = (const uint4*)(h_w + (size_t)e * 16);
        const uint4* pe = (const uint4*)(e_vw + (size_t)e * 16);
#pragma unroll
        for (int i = 0; i < 4; i++) {
            uint4 a = ph[i];
            hw2[2 * i]     = ((unsigned long long)a.y << 32) | a.x;
            hw2[2 * i + 1] = ((unsigned long long)a.w << 32) | a.z;
            uint4 b = pe[i];
            ev2[2 * i]     = ((unsigned long long)b.y << 32) | b.x;
            ev2[2 * i + 1] = ((unsigned long long)b.w << 32) | b.z;
        }
    }

    // Packed accumulators for m = 0..15; lane pairs accumulate over n pairs.
    unsigned long long acc2[NDIM];
#pragma unroll
    for (int m = 0; m < NDIM; m++) acc2[m] = 0ULL;

    for (int j = 0; j < HID; j++) {
        // ---- hidden unit j: hj = relu(b1[j] + e_vw . W1[:, j]) ----
        const unsigned long long* w1r =
            (const unsigned long long*)(sW1T + j * NDIM);
        unsigned long long t0 = 0ULL, t1 = 0ULL;
#pragma unroll
        for (int k = 0; k < 4; k++) {
            t0 = ffma2(w1r[2 * k],     ev2[2 * k],     t0);
            t1 = ffma2(w1r[2 * k + 1], ev2[2 * k + 1], t1);
        }
        unsigned long long ts = fadd2(t0, t1);
        float hj = lo32(ts) + hi32(ts) + sb1[j];
        hj = fmaxf(hj, 0.0f);
        unsigned long long hj2 = dup2(hj);

        // ---- acc[m] += hj * (W2[j, m*16 : m*16+16] . h_w) ----
        const unsigned long long* w2r =
            (const unsigned long long*)(sW2 + j * 256);
#pragma unroll
        for (int m = 0; m < NDIM; m++) {
            unsigned long long s0 = 0ULL, s1 = 0ULL;
#pragma unroll
            for (int q = 0; q < 4; q++) {
                s0 = ffma2(w2r[m * 8 + 2 * q],     hw2[2 * q],     s0);
                s1 = ffma2(w2r[m * 8 + 2 * q + 1], hw2[2 * q + 1], s1);
            }
            acc2[m] = ffma2(hj2, fadd2(s0, s1), acc2[m]);
        }
    }

    // ---- b2 contribution: acc[m] += b2[m*16 : m*16+16] . h_w ----
    {
        const unsigned long long* b2r = (const unsigned long long*)sb2;
#pragma unroll
        for (int m = 0; m < NDIM; m++) {
#pragma unroll
            for (int q = 0; q < 8; q++)
                acc2[m] = ffma2(b2r[m * 8 + q], hw2[q], acc2[m]);
        }
    }

    // ---- scatter-add to target node ----
    const int node = index_v[e];
    float* op = out + (size_t)node * NDIM;
#pragma unroll
    for (int m = 0; m < NDIM; m++) {
        atomicAdd(op + m, lo32(acc2[m]) + hi32(acc2[m]));
    }
}

// ---------------- launch ----------------
extern "C" void kernel_launch(void* const* d_in, const int* in_sizes, int n_in,
                              void* d_out, int out_size) {
    const int*   index_v = nullptr;
    const float* h_w = nullptr;
    const float* e_vw = nullptr;
    const float* W1 = nullptr;
    const float* b1 = nullptr;
    const float* W2 = nullptr;
    const float* b2 = nullptr;

    // Identify big inputs (index: n_edge elems; features: n_edge*16 elems).
    int big_idx[8];
    long long big_sz[8];
    int nb = 0;
    for (int i = 0; i < n_in; i++) {
        long long s = in_sizes[i];
        if (s == 1024)       W1 = (const float*)d_in[i];
        else if (s == 64)    b1 = (const float*)d_in[i];
        else if (s == 16384) W2 = (const float*)d_in[i];
        else if (s == 256)   b2 = (const float*)d_in[i];
        else if (s > 100000 && nb < 8) {
            big_idx[nb] = i;
            big_sz[nb] = s;
            nb++;
        }
        // size-1 scalar (n_node) ignored; n_node derived from out_size
    }

    // index_v = smallest big input; the remaining two, in metadata order,
    // are h_w then e_vw.
    long long min_sz = big_sz[0];
    int min_pos = 0;
    for (int i = 1; i < nb; i++)
        if (big_sz[i] < min_sz) { min_sz = big_sz[i]; min_pos = i; }
    index_v = (const int*)d_in[big_idx[min_pos]];
    int n_edge = (int)min_sz;
    bool got_h = false;
    for (int i = 0; i < nb; i++) {
        if (i == min_pos) continue;
        if (!got_h) { h_w = (const float*)d_in[big_idx[i]]; got_h = true; }
        else        { e_vw = (const float*)d_in[big_idx[i]]; }
    }

    float* out = (float*)d_out;

    // Zero the (poisoned) output.
    zero_out_kernel<<<(out_size + 255) / 256, 256>>>(out, out_size);

    // Main fused kernel.
    static bool attr_set = false;
    if (!attr_set) {
        cudaFuncSetAttribute(msg_kernel,
                             cudaFuncAttributeMaxDynamicSharedMemorySize,
                             SMEM_FLOATS * (int)sizeof(float));
        attr_set = true;
    }
    int blocks = (n_edge + TPB - 1) / TPB;
    msg_kernel<<<blocks, TPB, SMEM_FLOATS * sizeof(float)>>>(
        index_v, h_w, e_vw, W1, b1, W2, b2, out, n_edge);
}

// round 2
// speedup vs baseline: 1.0061x; 1.0061x over previous
#include <cuda_runtime.h>
#include <stdint.h>

// MessageFunction: per-edge MLP (16 -> 64 -> 256) -> reshape [16,16] -> matvec
// with h_w -> segment_sum over index_v into out [n_node, 16].
//
// Fused thread-per-edge kernel. Weights in dynamic shared memory, read with
// broadcast LDS.128. Inner products use packed fma.rn.f32x2 (sm_103a FFMA2).

#define NDIM 16
#define HID  64
#define TPB  256

// ---------------- f32x2 packed helpers ----------------
__device__ __forceinline__ unsigned long long ffma2(unsigned long long a,
                                                    unsigned long long b,
                                                    unsigned long long c) {
    unsigned long long d;
    asm("fma.rn.f32x2 %0, %1, %2, %3;" : "=l"(d) : "l"(a), "l"(b), "l"(c));
    return d;
}
__device__ __forceinline__ float lo32(unsigned long long v) {
    return __uint_as_float((unsigned)v);
}
__device__ __forceinline__ float hi32(unsigned long long v) {
    return __uint_as_float((unsigned)(v >> 32));
}
__device__ __forceinline__ unsigned long long dup2(float x) {
    unsigned u = __float_as_uint(x);
    return ((unsigned long long)u << 32) | (unsigned long long)u;
}

// ---------------- kernels ----------------
__global__ void zero_out_kernel(float* out, int n) {
    int i = blockIdx.x * blockDim.x + threadIdx.x;
    if (i < n) out[i] = 0.0f;
}

// Dynamic shared layout (floats), all 16B-aligned:
//   [0, 1024)        sW1T  [HID][NDIM]   (W1 transposed: [j][k])
//   [1024, 1088)     sb1   [HID]
//   [1088, 17472)    sW2   [HID][256]    (row-major, row j = 256 floats)
//   [17472, 17728)   sb2   [256]
#define SMEM_FLOATS 17728

extern "C" __global__ void __launch_bounds__(TPB)
msg_kernel(const int* __restrict__ index_v,
           const float* __restrict__ h_w,
           const float* __restrict__ e_vw,
           const float* __restrict__ W1,
           const float* __restrict__ b1,
           const float* __restrict__ W2,
           const float* __restrict__ b2,
           float* __restrict__ out,
           int n_edge) {
    extern __shared__ float smem[];
    float* sW1T = smem;            // [HID][NDIM]
    float* sb1  = smem + 1024;     // [HID]
    float* sW2  = smem + 1088;     // [HID][256]
    float* sb2  = smem + 17472;    // [256]

    const int tid = threadIdx.x;

    // Stage weights in shared. W1 arrives [k=16][j=64]; store transposed [j][k].
    for (int i = tid; i < NDIM * HID; i += TPB) {
        int k = i >> 6;     // row in W1
        int j = i & 63;     // col in W1
        sW1T[j * NDIM + k] = W1[i];
    }
    if (tid < HID) sb1[tid] = b1[tid];
    for (int i = tid; i < HID * 256; i += TPB) sW2[i] = W2[i];
    if (tid < 256) sb2[tid] = b2[tid];
    __syncthreads();

    const int e = blockIdx.x * TPB + tid;
    if (e >= n_edge) return;

    // Load this edge's h_w and e_vw rows as packed f32x2 pairs.
    unsigned long long hw2[8], ev2[8];
    {
        const uint4* ph = (const uint4*)(h_w + (size_t)e * 16);
        const uint4* pe = (const uint4*)(e_vw + (size_t)e * 16);
#pragma unroll
        for (int i = 0; i < 4; i++) {
            uint4 a = ph[i];
            hw2[2 * i]     = ((unsigned long long)a.y << 32) | a.x;
            hw2[2 * i + 1] = ((unsigned long long)a.w << 32) | a.z;
            uint4 b = pe[i];
            ev2[2 * i]     = ((unsigned long long)b.y << 32) | b.x;
            ev2[2 * i + 1] = ((unsigned long long)b.w << 32) | b.z;
        }
    }

    // Packed accumulators for m = 0..15.
    unsigned long long acc2[NDIM];
#pragma unroll
    for (int m = 0; m < NDIM; m++) acc2[m] = 0ULL;

    for (int j = 0; j < HID; j++) {
        // ---- hidden unit j: hj = relu(b1[j] + e_vw . W1[:, j]) ----
        // LDS.128 loads; two parallel chains for latency, one fadd at end
        // is folded into the scalar hsum anyway.
        const ulonglong2* w1r = (const ulonglong2*)(sW1T + j * NDIM);
        unsigned long long t0 = 0ULL, t1 = 0ULL;
#pragma unroll
        for (int k = 0; k < 4; k++) {
            ulonglong2 w = w1r[k];
            t0 = ffma2(w.x, ev2[2 * k],     t0);
            t1 = ffma2(w.y, ev2[2 * k + 1], t1);
        }
        float hj = (lo32(t0) + hi32(t0)) + (lo32(t1) + hi32(t1)) + sb1[j];
        hj = fmaxf(hj, 0.0f);
        const unsigned long long hj2 = dup2(hj);

        // ---- acc[m] += hj * (W2[j, m*16 : m*16+16] . h_w) ----
        // Single 8-deep ffma2 chain per m (16 independent chains = ILP),
        // LDS.128 for W2.
        const ulonglong2* w2r = (const ulonglong2*)(sW2 + j * 256);
#pragma unroll
        for (int m = 0; m < NDIM; m++) {
            ulonglong2 wa = w2r[m * 4 + 0];
            ulonglong2 wb = w2r[m * 4 + 1];
            ulonglong2 wc = w2r[m * 4 + 2];
            ulonglong2 wd = w2r[m * 4 + 3];
            unsigned long long s;
            s = ffma2(wa.x, hw2[0], 0ULL);
            s = ffma2(wa.y, hw2[1], s);
            s = ffma2(wb.x, hw2[2], s);
            s = ffma2(wb.y, hw2[3], s);
            s = ffma2(wc.x, hw2[4], s);
            s = ffma2(wc.y, hw2[5], s);
            s = ffma2(wd.x, hw2[6], s);
            s = ffma2(wd.y, hw2[7], s);
            acc2[m] = ffma2(hj2, s, acc2[m]);
        }
    }

    // ---- b2 contribution: acc[m] += b2[m*16 : m*16+16] . h_w ----
    {
        const ulonglong2* b2r = (const ulonglong2*)sb2;
#pragma unroll
        for (int m = 0; m < NDIM; m++) {
#pragma unroll
            for (int q = 0; q < 4; q++) {
                ulonglong2 w = b2r[m * 4 + q];
                acc2[m] = ffma2(w.x, hw2[2 * q],     acc2[m]);
                acc2[m] = ffma2(w.y, hw2[2 * q + 1], acc2[m]);
            }
        }
    }

    // ---- scatter-add to target node ----
    const int node = index_v[e];
    float* op = out + (size_t)node * NDIM;
#pragma unroll
    for (int m = 0; m < NDIM; m++) {
        atomicAdd(op + m, lo32(acc2[m]) + hi32(acc2[m]));
    }
}

// ---------------- launch ----------------
extern "C" void kernel_launch(void* const* d_in, const int* in_sizes, int n_in,
                              void* d_out, int out_size) {
    const int*   index_v = nullptr;
    const float* h_w = nullptr;
    const float* e_vw = nullptr;
    const float* W1 = nullptr;
    const float* b1 = nullptr;
    const float* W2 = nullptr;
    const float* b2 = nullptr;

    // Identify big inputs (index: n_edge elems; features: n_edge*16 elems).
    int big_idx[8];
    long long big_sz[8];
    int nb = 0;
    for (int i = 0; i < n_in; i++) {
        long long s = in_sizes[i];
        if (s == 1024)       W1 = (const float*)d_in[i];
        else if (s == 64)    b1 = (const float*)d_in[i];
        else if (s == 16384) W2 = (const float*)d_in[i];
        else if (s == 256)   b2 = (const float*)d_in[i];
        else if (s > 100000 && nb < 8) {
            big_idx[nb] = i;
            big_sz[nb] = s;
            nb++;
        }
    }

    // index_v = smallest big input; remaining two, in metadata order,
    // are h_w then e_vw.
    long long min_sz = big_sz[0];
    int min_pos = 0;
    for (int i = 1; i < nb; i++)
        if (big_sz[i] < min_sz) { min_sz = big_sz[i]; min_pos = i; }
    index_v = (const int*)d_in[big_idx[min_pos]];
    int n_edge = (int)min_sz;
    bool got_h = false;
    for (int i = 0; i < nb; i++) {
        if (i == min_pos) continue;
        if (!got_h) { h_w = (const float*)d_in[big_idx[i]]; got_h = true; }
        else        { e_vw = (const float*)d_in[big_idx[i]]; }
    }

    float* out = (float*)d_out;

    // Zero the (poisoned) output.
    zero_out_kernel<<<(out_size + 255) / 256, 256>>>(out, out_size);

    static bool attr_set = false;
    if (!attr_set) {
        cudaFuncSetAttribute(msg_kernel,
                             cudaFuncAttributeMaxDynamicSharedMemorySize,
                             SMEM_FLOATS * (int)sizeof(float));
        attr_set = true;
    }
    int blocks = (n_edge + TPB - 1) / TPB;
    msg_kernel<<<blocks, TPB, SMEM_FLOATS * sizeof(float)>>>(
        index_v, h_w, e_vw, W1, b1, W2, b2, out, n_edge);
}

// round 4
// speedup vs baseline: 4.1292x; 4.1041x over previous
#include <cuda_runtime.h>
#include <stdint.h>

// MessageFunction via portable mma.sync (tf32) — harness targets plain sm_103,
// so tcgen05 is unavailable; m16n8k8 tf32 mma.sync (sm_80+) is the tensor path.
//
// Persistent CTAs. Weights staged once into smem in B-FRAGMENT-major layout
// (one LDS.64 per fragment, conflict-free). Per 256-edge tile:
//   GEMM1: e[256,16] x W1[16,64] -> hid (mma, 2 k-steps)
//   relu + bias + cvt.tf32 -> warp-private smem in A-fragment layout
//   GEMM2: hid[256,64] x W2[64,256] -> A_vw (mma, 8 k-steps, 4 N-chunks)
//   epilogue: + b2, matvec with h_w (regs), quad shfl reduce,
//             red.global.add.v4.f32 scatter into out[n_node,16].

#define TPB   256
#define TILE  256

// ---- smem float offsets ----
#define OF_W2F  0        // 16384 fl: W2 B-frags [ks(8)][nt(32)][lane(32)][2]
#define OF_W1F  16384    // 1024 fl : W1 B-frags [ks(2)][nt(8)][lane(32)][2]
#define OF_B1   17408    // 64
#define OF_B2   17472    // 256
#define OF_H    17728    // 4096 fl : h tile [256][16]
#define OF_EF   21824    // 4096 fl : e A-frags [wp*2+mt][ks(2)][lane(32)][4]
#define OF_HID  25920    // 16384 fl: hid A-frags, per-warp 2048 [mt*8+ks][lane][4]
#define SMEM_FLOATS 42304   // 169216 bytes

__device__ __forceinline__ float cvt_tf32f(float x) {
    uint32_t r;
    asm("cvt.rna.tf32.f32 %0, %1;" : "=r"(r) : "f"(x));
    return __uint_as_float(r);
}

#define MMA_TF32(d, a, b0, b1) \
    asm volatile("mma.sync.aligned.m16n8k8.row.col.f32.tf32.tf32.f32 " \
        "{%0,%1,%2,%3}, {%4,%5,%6,%7}, {%8,%9}, {%0,%1,%2,%3};" \
        : "+f"((d)[0]), "+f"((d)[1]), "+f"((d)[2]), "+f"((d)[3]) \
        : "r"((a)[0]), "r"((a)[1]), "r"((a)[2]), "r"((a)[3]), \
          "r"(b0), "r"(b1))

__device__ __forceinline__ void red_add_v4(float* p, float a, float b,
                                           float c, float d) {
    asm volatile("red.global.add.v4.f32 [%0], {%1,%2,%3,%4};"
                 :: "l"(p), "f"(a), "f"(b), "f"(c), "f"(d) : "memory");
}

__global__ void zero_out_kernel(float* out, int n) {
    int i = blockIdx.x * blockDim.x + threadIdx.x;
    if (i < n) out[i] = 0.0f;
}

extern "C" __global__ void __launch_bounds__(TPB, 1)
msg_mma_kernel(const int* __restrict__ index_v,
               const float* __restrict__ h_w,
               const float* __restrict__ e_vw,
               const float* __restrict__ W1,
               const float* __restrict__ b1,
               const float* __restrict__ W2,
               const float* __restrict__ b2,
               float* __restrict__ out,
               int n_edge) {
    extern __shared__ float sm[];
    const int tid  = threadIdx.x;
    const int warp = tid >> 5;
    const int lane = tid & 31;
    const int q = lane & 3;       // quad col
    const int g = lane >> 2;      // group row

    // ================= stage weights (once per CTA) =================
    // W2 B-frags: b0 = W2[ks*8+q][nt*8+g], b1 = W2[ks*8+q+4][nt*8+g]
    for (int s = tid; s < 8192; s += TPB) {
        int ln = s & 31, nt = (s >> 5) & 31, ks = s >> 10;
        int qq = ln & 3, gg = ln >> 2;
        sm[OF_W2F + 2 * s]     = cvt_tf32f(W2[(ks * 8 + qq)     * 256 + nt * 8 + gg]);
        sm[OF_W2F + 2 * s + 1] = cvt_tf32f(W2[(ks * 8 + qq + 4) * 256 + nt * 8 + gg]);
    }
    // W1 B-frags: W1 is [k=16][j=64] row-major
    for (int s = tid; s < 512; s += TPB) {
        int ln = s & 31, nt = (s >> 5) & 7, ks = s >> 8;
        int qq = ln & 3, gg = ln >> 2;
        sm[OF_W1F + 2 * s]     = cvt_tf32f(W1[(ks * 8 + qq)     * 64 + nt * 8 + gg]);
        sm[OF_W1F + 2 * s + 1] = cvt_tf32f(W1[(ks * 8 + qq + 4) * 64 + nt * 8 + gg]);
    }
    if (tid < 64)  sm[OF_B1 + tid] = b1[tid];
    if (tid < 256) sm[OF_B2 + tid] = b2[tid];
    __syncthreads();

    const int ntiles = (n_edge + TILE - 1) / TILE;

    for (int t = blockIdx.x; t < ntiles; t += gridDim.x) {
        const int base = t * TILE;
        const int rem  = n_edge - base;

        // ---- stage e (A-frag layout, tf32) and h (row-major) ----
        {
            const int row = tid;
            const int sr  = row < rem ? row : rem - 1;
            float ev[16];
            const float4* ep = (const float4*)(e_vw + (size_t)(base + sr) * 16);
#pragma unroll
            for (int i = 0; i < 4; i++) {
                float4 v = __ldg(ep + i);
                ev[4 * i + 0] = cvt_tf32f(v.x);
                ev[4 * i + 1] = cvt_tf32f(v.y);
                ev[4 * i + 2] = cvt_tf32f(v.z);
                ev[4 * i + 3] = cvt_tf32f(v.w);
            }
            const int wp = row >> 5, mt = (row >> 4) & 1;
            const int gg = row & 7,  r0 = (row >> 3) & 1;
#pragma unroll
            for (int col = 0; col < 16; col++) {
                int ks = col >> 3, qq = col & 3, r1 = (col >> 2) & 1;
                sm[OF_EF + (((wp * 2 + mt) * 2 + ks) * 32 + ((gg << 2) | qq)) * 4
                   + (r0 | (r1 << 1))] = ev[col];
            }
            const float4* hp = (const float4*)(h_w + (size_t)(base + sr) * 16);
            float4* hd = (float4*)(sm + OF_H + row * 16);
#pragma unroll
            for (int i = 0; i < 4; i++) hd[i] = __ldg(hp + i);
        }
        __syncthreads();

        // ---- GEMM1: hid[32 rows x 64] per warp ----
        uint32_t ea[2][2][4];
#pragma unroll
        for (int mt = 0; mt < 2; mt++)
#pragma unroll
            for (int ks = 0; ks < 2; ks++) {
                uint4 v = ((const uint4*)(sm + OF_EF))[((warp * 2 + mt) * 2 + ks) * 32 + lane];
                ea[mt][ks][0] = v.x; ea[mt][ks][1] = v.y;
                ea[mt][ks][2] = v.z; ea[mt][ks][3] = v.w;
            }
        float acc1[2][8][4];
#pragma unroll
        for (int mt = 0; mt < 2; mt++)
#pragma unroll
            for (int nt = 0; nt < 8; nt++)
#pragma unroll
                for (int r = 0; r < 4; r++) acc1[mt][nt][r] = 0.0f;
#pragma unroll
        for (int ks = 0; ks < 2; ks++)
#pragma unroll
            for (int nt = 0; nt < 8; nt++) {
                uint2 b = ((const uint2*)(sm + OF_W1F))[(ks * 8 + nt) * 32 + lane];
                MMA_TF32(acc1[0][nt], ea[0][ks], b.x, b.y);
                MMA_TF32(acc1[1][nt], ea[1][ks], b.x, b.y);
            }

        // ---- bias + relu + cvt, store to warp-private A-frag smem ----
        float* hid = sm + OF_HID + warp * 2048;
#pragma unroll
        for (int mt = 0; mt < 2; mt++)
#pragma unroll
            for (int nt = 0; nt < 8; nt++) {
                float2 bb = *(const float2*)(sm + OF_B1 + nt * 8 + 2 * q);
#pragma unroll
                for (int s = 0; s < 2; s++)
#pragma unroll
                    for (int e2 = 0; e2 < 2; e2++) {
                        float v = acc1[mt][nt][2 * s + e2] + (e2 ? bb.y : bb.x);
                        v = cvt_tf32f(fmaxf(v, 0.0f));
                        int col2 = 2 * q + e2;                 // col within n-tile
                        int lp = (g << 2) | (col2 & 3);
                        int rr = s | ((col2 >> 2) << 1);
                        hid[((mt * 8 + nt) * 32 + lp) * 4 + rr] = v;
                    }
            }
        __syncwarp();

        // ---- GEMM2 A-frags (resident), h regs, nodes ----
        uint32_t ha[2][8][4];
#pragma unroll
        for (int mt = 0; mt < 2; mt++)
#pragma unroll
            for (int ks = 0; ks < 8; ks++) {
                uint4 v = ((const uint4*)hid)[(mt * 8 + ks) * 32 + lane];
                ha[mt][ks][0] = v.x; ha[mt][ks][1] = v.y;
                ha[mt][ks][2] = v.z; ha[mt][ks][3] = v.w;
            }
        float hreg[2][2][4];
        int   node[2][2];
        bool  vld[2][2];
#pragma unroll
        for (int mt = 0; mt < 2; mt++)
#pragma unroll
            for (int rr = 0; rr < 2; rr++) {
                int row = warp * 32 + mt * 16 + g + rr * 8;
                float2 h0 = *(const float2*)(sm + OF_H + row * 16 + 2 * q);
                float2 h1 = *(const float2*)(sm + OF_H + row * 16 + 8 + 2 * q);
                hreg[mt][rr][0] = h0.x; hreg[mt][rr][1] = h0.y;
                hreg[mt][rr][2] = h1.x; hreg[mt][rr][3] = h1.y;
                int ge = base + row;
                vld[mt][rr]  = ge < n_edge;
                node[mt][rr] = vld[mt][rr] ? __ldg(index_v + ge) : 0;
            }

        // ---- GEMM2 + epilogue, 4 chunks of 64 cols ----
#pragma unroll
        for (int c = 0; c < 4; c++) {
            float acc[2][8][4];
#pragma unroll
            for (int mt = 0; mt < 2; mt++)
#pragma unroll
                for (int nt = 0; nt < 8; nt++)
#pragma unroll
                    for (int r = 0; r < 4; r++) acc[mt][nt][r] = 0.0f;
#pragma unroll
            for (int ks = 0; ks < 8; ks++)
#pragma unroll
                for (int nt = 0; nt < 8; nt++) {
                    uint2 b = ((const uint2*)(sm + OF_W2F))[(ks * 32 + c * 8 + nt) * 32 + lane];
                    MMA_TF32(acc[0][nt], ha[0][ks], b.x, b.y);
                    MMA_TF32(acc[1][nt], ha[1][ks], b.x, b.y);
                }
            float pacc[2][2][4];
#pragma unroll
            for (int mt = 0; mt < 2; mt++)
#pragma unroll
                for (int rr = 0; rr < 2; rr++)
#pragma unroll
                    for (int ml = 0; ml < 4; ml++) pacc[mt][rr][ml] = 0.0f;
#pragma unroll
            for (int mt = 0; mt < 2; mt++)
#pragma unroll
                for (int nt = 0; nt < 8; nt++) {
                    int ntg = c * 8 + nt;
                    float2 bb = *(const float2*)(sm + OF_B2 + ntg * 8 + 2 * q);
                    int hb = (nt & 1) * 2;
                    int ml = nt >> 1;
                    pacc[mt][0][ml] = fmaf(acc[mt][nt][0] + bb.x, hreg[mt][0][hb],     pacc[mt][0][ml]);
                    pacc[mt][0][ml] = fmaf(acc[mt][nt][1] + bb.y, hreg[mt][0][hb + 1], pacc[mt][0][ml]);
                    pacc[mt][1][ml] = fmaf(acc[mt][nt][2] + bb.x, hreg[mt][1][hb],     pacc[mt][1][ml]);
                    pacc[mt][1][ml] = fmaf(acc[mt][nt][3] + bb.y, hreg[mt][1][hb + 1], pacc[mt][1][ml]);
                }
#pragma unroll
            for (int mt = 0; mt < 2; mt++)
#pragma unroll
                for (int rr = 0; rr < 2; rr++) {
#pragma unroll
                    for (int ml = 0; ml < 4; ml++) {
                        float v = pacc[mt][rr][ml];
                        v += __shfl_xor_sync(0xFFFFFFFFu, v, 1);
                        v += __shfl_xor_sync(0xFFFFFFFFu, v, 2);
                        pacc[mt][rr][ml] = v;
                    }
                    if (q == 0 && vld[mt][rr]) {
                        red_add_v4(out + (size_t)node[mt][rr] * 16 + c * 4,
                                   pacc[mt][rr][0], pacc[mt][rr][1],
                                   pacc[mt][rr][2], pacc[mt][rr][3]);
                    }
                }
        }
        __syncthreads();  // protect sH/sEF before next tile restage
    }
}

// ---------------- launch ----------------
extern "C" void kernel_launch(void* const* d_in, const int* in_sizes, int n_in,
                              void* d_out, int out_size) {
    const int*   index_v = nullptr;
    const float* h_w = nullptr;
    const float* e_vw = nullptr;
    const float* W1 = nullptr;
    const float* b1 = nullptr;
    const float* W2 = nullptr;
    const float* b2 = nullptr;

    int big_idx[8]; long long big_sz[8]; int nb = 0;
    for (int i = 0; i < n_in; i++) {
        long long s = in_sizes[i];
        if (s == 1024)       W1 = (const float*)d_in[i];
        else if (s == 64)    b1 = (const float*)d_in[i];
        else if (s == 16384) W2 = (const float*)d_in[i];
        else if (s == 256)   b2 = (const float*)d_in[i];
        else if (s > 100000 && nb < 8) { big_idx[nb] = i; big_sz[nb] = s; nb++; }
    }
    long long min_sz = big_sz[0]; int min_pos = 0;
    for (int i = 1; i < nb; i++)
        if (big_sz[i] < min_sz) { min_sz = big_sz[i]; min_pos = i; }
    index_v = (const int*)d_in[big_idx[min_pos]];
    int n_edge = (int)min_sz;
    bool got_h = false;
    for (int i = 0; i < nb; i++) {
        if (i == min_pos) continue;
        if (!got_h) { h_w = (const float*)d_in[big_idx[i]]; got_h = true; }
        else        { e_vw = (const float*)d_in[big_idx[i]]; }
    }

    float* out = (float*)d_out;
    zero_out_kernel<<<(out_size + 255) / 256, 256>>>(out, out_size);

    static bool attr_set = false;
    if (!attr_set) {
        cudaFuncSetAttribute(msg_mma_kernel,
                             cudaFuncAttributeMaxDynamicSharedMemorySize,
                             SMEM_FLOATS * (int)sizeof(float));
        attr_set = true;
    }
    int ntiles = (n_edge + TILE - 1) / TILE;
    int grid = ntiles < 152 ? ntiles : 152;
    msg_mma_kernel<<<grid, TPB, SMEM_FLOATS * sizeof(float)>>>(
        index_v, h_w, e_vw, W1, b1, W2, b2, out, n_edge);
}

// round 5
// speedup vs baseline: 4.2572x; 1.0310x over previous
#include <cuda_runtime.h>
#include <stdint.h>

// MessageFunction via portable mma.sync (tf32), persistent CTAs.
// R5: software-pipelined tile staging (double-buffered e-frags + h),
//     non-volatile MMA asm (lets ptxas schedule across epilogue),
//     single __syncthreads per tile, memset-based output zeroing.

#define TPB   256
#define TILE  256

// ---- smem float offsets ----
#define OF_W2F  0        // 16384 fl: W2 B-frags [ks(8)][nt(32)][lane(32)][2]
#define OF_W1F  16384    // 1024 fl : W1 B-frags [ks(2)][nt(8)][lane(32)][2]
#define OF_B1   17408    // 64
#define OF_B2   17472    // 256
#define OF_H    17728    // 2 x 4096 fl : h tile [256][16], double buffered
#define OF_EF   25920    // 2 x 4096 fl : e A-frags, double buffered
#define OF_HID  34112    // 16384 fl: hid A-frags, per-warp 2048
#define SMEM_FLOATS 50496   // 201984 bytes

__device__ __forceinline__ float cvt_tf32f(float x) {
    uint32_t r;
    asm("cvt.rna.tf32.f32 %0, %1;" : "=r"(r) : "f"(x));
    return __uint_as_float(r);
}

// NOT volatile: pure register computation; let ptxas pipeline it.
#define MMA_TF32(d, a, b0, b1) \
    asm("mma.sync.aligned.m16n8k8.row.col.f32.tf32.tf32.f32 " \
        "{%0,%1,%2,%3}, {%4,%5,%6,%7}, {%8,%9}, {%0,%1,%2,%3};" \
        : "+f"((d)[0]), "+f"((d)[1]), "+f"((d)[2]), "+f"((d)[3]) \
        : "r"((a)[0]), "r"((a)[1]), "r"((a)[2]), "r"((a)[3]), \
          "r"(b0), "r"(b1))

__device__ __forceinline__ void red_add_v4(float* p, float a, float b,
                                           float c, float d) {
    asm volatile("red.global.add.v4.f32 [%0], {%1,%2,%3,%4};"
                 :: "l"(p), "f"(a), "f"(b), "f"(c), "f"(d) : "memory");
}

extern "C" __global__ void __launch_bounds__(TPB, 1)
msg_mma_kernel(const int* __restrict__ index_v,
               const float* __restrict__ h_w,
               const float* __restrict__ e_vw,
               const float* __restrict__ W1,
               const float* __restrict__ b1,
               const float* __restrict__ W2,
               const float* __restrict__ b2,
               float* __restrict__ out,
               int n_edge) {
    extern __shared__ float sm[];
    const int tid  = threadIdx.x;
    const int warp = tid >> 5;
    const int lane = tid & 31;
    const int q = lane & 3;       // quad col
    const int g = lane >> 2;      // group row

    // ================= stage weights (once per CTA) =================
    for (int s = tid; s < 8192; s += TPB) {
        int ln = s & 31, nt = (s >> 5) & 31, ks = s >> 10;
        int qq = ln & 3, gg = ln >> 2;
        sm[OF_W2F + 2 * s]     = cvt_tf32f(W2[(ks * 8 + qq)     * 256 + nt * 8 + gg]);
        sm[OF_W2F + 2 * s + 1] = cvt_tf32f(W2[(ks * 8 + qq + 4) * 256 + nt * 8 + gg]);
    }
    for (int s = tid; s < 512; s += TPB) {
        int ln = s & 31, nt = (s >> 5) & 7, ks = s >> 8;
        int qq = ln & 3, gg = ln >> 2;
        sm[OF_W1F + 2 * s]     = cvt_tf32f(W1[(ks * 8 + qq)     * 64 + nt * 8 + gg]);
        sm[OF_W1F + 2 * s + 1] = cvt_tf32f(W1[(ks * 8 + qq + 4) * 64 + nt * 8 + gg]);
    }
    if (tid < 64)  sm[OF_B1 + tid] = b1[tid];
    if (tid < 256) sm[OF_B2 + tid] = b2[tid];

    const int ntiles = (n_edge + TILE - 1) / TILE;

    // per-thread staging geometry (row = tid)
    const int s_wp = tid >> 5, s_mt = (tid >> 4) & 1;
    const int s_gg = tid & 7,  s_r0 = (tid >> 3) & 1;

    // ---- prologue: stage first tile into buffer 0 ----
    {
        const int t0 = blockIdx.x;
        if (t0 < ntiles) {
            const int base = t0 * TILE;
            const int rem  = n_edge - base;
            const int sr   = tid < rem ? tid : rem - 1;
            const float4* ep = (const float4*)(e_vw + (size_t)(base + sr) * 16);
            const float4* hp = (const float4*)(h_w + (size_t)(base + sr) * 16);
            float ev[16];
#pragma unroll
            for (int i = 0; i < 4; i++) {
                float4 v = __ldg(ep + i);
                ev[4 * i + 0] = cvt_tf32f(v.x); ev[4 * i + 1] = cvt_tf32f(v.y);
                ev[4 * i + 2] = cvt_tf32f(v.z); ev[4 * i + 3] = cvt_tf32f(v.w);
            }
#pragma unroll
            for (int col = 0; col < 16; col++) {
                int ks = col >> 3, qq = col & 3, r1 = (col >> 2) & 1;
                sm[OF_EF + (((s_wp * 2 + s_mt) * 2 + ks) * 32 + ((s_gg << 2) | qq)) * 4
                   + (s_r0 | (r1 << 1))] = ev[col];
            }
            float4* hd = (float4*)(sm + OF_H + tid * 16);
#pragma unroll
            for (int i = 0; i < 4; i++) hd[i] = __ldg(hp + i);
        }
    }
    __syncthreads();

    int it = 0;
    for (int t = blockIdx.x; t < ntiles; t += gridDim.x, it++) {
        const int base = t * TILE;
        const int buf  = it & 1;
        const int nbuf = buf ^ 1;
        const float* EF = sm + OF_EF + buf * 4096;
        const float* H  = sm + OF_H  + buf * 4096;

        // ---- load GEMM1 A-frags from current buffer ----
        uint32_t ea[2][2][4];
#pragma unroll
        for (int mt = 0; mt < 2; mt++)
#pragma unroll
            for (int ks = 0; ks < 2; ks++) {
                uint4 v = ((const uint4*)EF)[((warp * 2 + mt) * 2 + ks) * 32 + lane];
                ea[mt][ks][0] = v.x; ea[mt][ks][1] = v.y;
                ea[mt][ks][2] = v.z; ea[mt][ks][3] = v.w;
            }

        // ---- issue next-tile global loads NOW (hide under GEMM1/epi1) ----
        const int tn = t + gridDim.x;
        const bool has_next = tn < ntiles;
        float evn[16], hvn[16];
        if (has_next) {
            const int nb2 = tn * TILE;
            const int rem2 = n_edge - nb2;
            const int sr2  = tid < rem2 ? tid : rem2 - 1;
            const float4* ep = (const float4*)(e_vw + (size_t)(nb2 + sr2) * 16);
            const float4* hp = (const float4*)(h_w + (size_t)(nb2 + sr2) * 16);
#pragma unroll
            for (int i = 0; i < 4; i++) {
                float4 v = __ldg(ep + i);
                evn[4 * i + 0] = v.x; evn[4 * i + 1] = v.y;
                evn[4 * i + 2] = v.z; evn[4 * i + 3] = v.w;
                float4 h = __ldg(hp + i);
                hvn[4 * i + 0] = h.x; hvn[4 * i + 1] = h.y;
                hvn[4 * i + 2] = h.z; hvn[4 * i + 3] = h.w;
            }
        }

        // ---- GEMM1: hid[32 rows x 64] per warp ----
        float acc1[2][8][4];
#pragma unroll
        for (int mt = 0; mt < 2; mt++)
#pragma unroll
            for (int nt = 0; nt < 8; nt++)
#pragma unroll
                for (int r = 0; r < 4; r++) acc1[mt][nt][r] = 0.0f;
#pragma unroll
        for (int ks = 0; ks < 2; ks++)
#pragma unroll
            for (int nt = 0; nt < 8; nt++) {
                uint2 b = ((const uint2*)(sm + OF_W1F))[(ks * 8 + nt) * 32 + lane];
                MMA_TF32(acc1[0][nt], ea[0][ks], b.x, b.y);
                MMA_TF32(acc1[1][nt], ea[1][ks], b.x, b.y);
            }

        // ---- bias + relu + cvt, store to warp-private A-frag smem ----
        float* hid = sm + OF_HID + warp * 2048;
#pragma unroll
        for (int mt = 0; mt < 2; mt++)
#pragma unroll
            for (int nt = 0; nt < 8; nt++) {
                float2 bb = *(const float2*)(sm + OF_B1 + nt * 8 + 2 * q);
#pragma unroll
                for (int s = 0; s < 2; s++)
#pragma unroll
                    for (int e2 = 0; e2 < 2; e2++) {
                        float v = acc1[mt][nt][2 * s + e2] + (e2 ? bb.y : bb.x);
                        v = cvt_tf32f(fmaxf(v, 0.0f));
                        int col2 = 2 * q + e2;
                        int lp = (g << 2) | (col2 & 3);
                        int rr = s | ((col2 >> 2) << 1);
                        hid[((mt * 8 + nt) * 32 + lp) * 4 + rr] = v;
                    }
            }
        __syncwarp();

        // ---- GEMM2 A-frags (resident), h regs, nodes ----
        uint32_t ha[2][8][4];
#pragma unroll
        for (int mt = 0; mt < 2; mt++)
#pragma unroll
            for (int ks = 0; ks < 8; ks++) {
                uint4 v = ((const uint4*)hid)[(mt * 8 + ks) * 32 + lane];
                ha[mt][ks][0] = v.x; ha[mt][ks][1] = v.y;
                ha[mt][ks][2] = v.z; ha[mt][ks][3] = v.w;
            }
        float hreg[2][2][4];
        int   node[2][2];
        bool  vld[2][2];
#pragma unroll
        for (int mt = 0; mt < 2; mt++)
#pragma unroll
            for (int rr = 0; rr < 2; rr++) {
                int row = warp * 32 + mt * 16 + g + rr * 8;
                float2 h0 = *(const float2*)(H + row * 16 + 2 * q);
                float2 h1 = *(const float2*)(H + row * 16 + 8 + 2 * q);
                hreg[mt][rr][0] = h0.x; hreg[mt][rr][1] = h0.y;
                hreg[mt][rr][2] = h1.x; hreg[mt][rr][3] = h1.y;
                int ge = base + row;
                vld[mt][rr]  = ge < n_edge;
                node[mt][rr] = vld[mt][rr] ? __ldg(index_v + ge) : 0;
            }

        // ---- store next-tile staging into the other buffer ----
        if (has_next) {
            float* EFn = sm + OF_EF + nbuf * 4096;
            float* Hn  = sm + OF_H  + nbuf * 4096;
#pragma unroll
            for (int col = 0; col < 16; col++) {
                int ks = col >> 3, qq = col & 3, r1 = (col >> 2) & 1;
                EFn[(((s_wp * 2 + s_mt) * 2 + ks) * 32 + ((s_gg << 2) | qq)) * 4
                    + (s_r0 | (r1 << 1))] = cvt_tf32f(evn[col]);
            }
            float4* hd = (float4*)(Hn + tid * 16);
#pragma unroll
            for (int i = 0; i < 4; i++)
                hd[i] = make_float4(hvn[4 * i], hvn[4 * i + 1],
                                    hvn[4 * i + 2], hvn[4 * i + 3]);
        }

        // ---- GEMM2 + epilogue, 4 chunks of 64 cols ----
#pragma unroll
        for (int c = 0; c < 4; c++) {
            float acc[2][8][4];
#pragma unroll
            for (int mt = 0; mt < 2; mt++)
#pragma unroll
                for (int nt = 0; nt < 8; nt++)
#pragma unroll
                    for (int r = 0; r < 4; r++) acc[mt][nt][r] = 0.0f;
#pragma unroll
            for (int ks = 0; ks < 8; ks++)
#pragma unroll
                for (int nt = 0; nt < 8; nt++) {
                    uint2 b = ((const uint2*)(sm + OF_W2F))[(ks * 32 + c * 8 + nt) * 32 + lane];
                    MMA_TF32(acc[0][nt], ha[0][ks], b.x, b.y);
                    MMA_TF32(acc[1][nt], ha[1][ks], b.x, b.y);
                }
            float pacc[2][2][4];
#pragma unroll
            for (int mt = 0; mt < 2; mt++)
#pragma unroll
                for (int rr = 0; rr < 2; rr++)
#pragma unroll
                    for (int ml = 0; ml < 4; ml++) pacc[mt][rr][ml] = 0.0f;
#pragma unroll
            for (int mt = 0; mt < 2; mt++)
#pragma unroll
                for (int nt = 0; nt < 8; nt++) {
                    int ntg = c * 8 + nt;
                    float2 bb = *(const float2*)(sm + OF_B2 + ntg * 8 + 2 * q);
                    int hb = (nt & 1) * 2;
                    int ml = nt >> 1;
                    pacc[mt][0][ml] = fmaf(acc[mt][nt][0] + bb.x, hreg[mt][0][hb],     pacc[mt][0][ml]);
                    pacc[mt][0][ml] = fmaf(acc[mt][nt][1] + bb.y, hreg[mt][0][hb + 1], pacc[mt][0][ml]);
                    pacc[mt][1][ml] = fmaf(acc[mt][nt][2] + bb.x, hreg[mt][1][hb],     pacc[mt][1][ml]);
                    pacc[mt][1][ml] = fmaf(acc[mt][nt][3] + bb.y, hreg[mt][1][hb + 1], pacc[mt][1][ml]);
                }
#pragma unroll
            for (int mt = 0; mt < 2; mt++)
#pragma unroll
                for (int rr = 0; rr < 2; rr++) {
#pragma unroll
                    for (int ml = 0; ml < 4; ml++) {
                        float v = pacc[mt][rr][ml];
                        v += __shfl_xor_sync(0xFFFFFFFFu, v, 1);
                        v += __shfl_xor_sync(0xFFFFFFFFu, v, 2);
                        pacc[mt][rr][ml] = v;
                    }
                    if (q == 0 && vld[mt][rr]) {
                        red_add_v4(out + (size_t)node[mt][rr] * 16 + c * 4,
                                   pacc[mt][rr][0], pacc[mt][rr][1],
                                   pacc[mt][rr][2], pacc[mt][rr][3]);
                    }
                }
        }
        __syncthreads();  // next-buffer staging visible; cur buffer reads done
    }
}

// ---------------- launch ----------------
extern "C" void kernel_launch(void* const* d_in, const int* in_sizes, int n_in,
                              void* d_out, int out_size) {
    const int*   index_v = nullptr;
    const float* h_w = nullptr;
    const float* e_vw = nullptr;
    const float* W1 = nullptr;
    const float* b1 = nullptr;
    const float* W2 = nullptr;
    const float* b2 = nullptr;

    int big_idx[8]; long long big_sz[8]; int nb = 0;
    for (int i = 0; i < n_in; i++) {
        long long s = in_sizes[i];
        if (s == 1024)       W1 = (const float*)d_in[i];
        else if (s == 64)    b1 = (const float*)d_in[i];
        else if (s == 16384) W2 = (const float*)d_in[i];
        else if (s == 256)   b2 = (const float*)d_in[i];
        else if (s > 100000 && nb < 8) { big_idx[nb] = i; big_sz[nb] = s; nb++; }
    }
    long long min_sz = big_sz[0]; int min_pos = 0;
    for (int i = 1; i < nb; i++)
        if (big_sz[i] < min_sz) { min_sz = big_sz[i]; min_pos = i; }
    index_v = (const int*)d_in[big_idx[min_pos]];
    int n_edge = (int)min_sz;
    bool got_h = false;
    for (int i = 0; i < nb; i++) {
        if (i == min_pos) continue;
        if (!got_h) { h_w = (const float*)d_in[big_idx[i]]; got_h = true; }
        else        { e_vw = (const float*)d_in[big_idx[i]]; }
    }

    float* out = (float*)d_out;
    cudaMemsetAsync(out, 0, (size_t)out_size * sizeof(float));

    static bool attr_set = false;
    if (!attr_set) {
        cudaFuncSetAttribute(msg_mma_kernel,
                             cudaFuncAttributeMaxDynamicSharedMemorySize,
                             SMEM_FLOATS * (int)sizeof(float));
        attr_set = true;
    }
    int ntiles = (n_edge + TILE - 1) / TILE;
    int grid = ntiles < 152 ? ntiles : 152;
    msg_mma_kernel<<<grid, TPB, SMEM_FLOATS * sizeof(float)>>>(
        index_v, h_w, e_vw, W1, b1, W2, b2, out, n_edge);
}

// round 6
// speedup vs baseline: 6.9108x; 1.6233x over previous
#include <cuda_runtime.h>
#include <cuda_fp16.h>
#include <stdint.h>

// MessageFunction via mma.sync m16n8k16 fp16 (fp32 accum), persistent CTAs.
// R6: fp16 MMA halves instruction count vs tf32 (same 11-bit significand);
//     GEMM1 output fragments convert in-register to GEMM2 A fragments
//     (no smem round trip). Double-buffered staging retained.

#define TPB   256
#define TILE  256

// ---- smem float offsets ----
#define OF_W2F  0        // 8192 fl: W2 B-frags uint2[ks(4)][ntg(32)][lane(32)]
#define OF_W1F  8192     // 512 fl : W1 B-frags uint2[nt(8)][lane(32)]
#define OF_B1   8704     // 64
#define OF_B2   8768     // 256
#define OF_H    9024     // 2 x 4096 fl : h tile [256][16] f32, double buffered
#define OF_E    17216    // 2 x 2048 fl : e tile [256][16] f16, double buffered
#define SMEM_FLOATS 21312   // 85248 bytes

__device__ __forceinline__ uint32_t pack_h2(float a, float b) {
    __half2 h = __floats2half2_rn(a, b);
    return *(uint32_t*)&h;
}

// Not volatile: pure register computation; let ptxas pipeline it.
#define MMA_F16(d, a, b0, b1) \
    asm("mma.sync.aligned.m16n8k16.row.col.f32.f16.f16.f32 " \
        "{%0,%1,%2,%3}, {%4,%5,%6,%7}, {%8,%9}, {%0,%1,%2,%3};" \
        : "+f"((d)[0]), "+f"((d)[1]), "+f"((d)[2]), "+f"((d)[3]) \
        : "r"((a)[0]), "r"((a)[1]), "r"((a)[2]), "r"((a)[3]), \
          "r"(b0), "r"(b1))

__device__ __forceinline__ void red_add_v4(float* p, float a, float b,
                                           float c, float d) {
    asm volatile("red.global.add.v4.f32 [%0], {%1,%2,%3,%4};"
                 :: "l"(p), "f"(a), "f"(b), "f"(c), "f"(d) : "memory");
}

extern "C" __global__ void __launch_bounds__(TPB, 1)
msg_mma_kernel(const int* __restrict__ index_v,
               const float* __restrict__ h_w,
               const float* __restrict__ e_vw,
               const float* __restrict__ W1,
               const float* __restrict__ b1,
               const float* __restrict__ W2,
               const float* __restrict__ b2,
               float* __restrict__ out,
               int n_edge) {
    extern __shared__ float sm[];
    const int tid  = threadIdx.x;
    const int warp = tid >> 5;
    const int lane = tid & 31;
    const int q = lane & 3;       // quad col (t)
    const int g = lane >> 2;      // group row

    // ================= stage weight fragments (once per CTA) =================
    // B frag (m16n8k16): b0 = {B[2q][n], B[2q+1][n]}, b1 = {B[2q+8][n], B[2q+9][n]}
    // W2 [64][256]: frag (ks, ntg): rows ks*16 + ..., n = ntg*8 + g
    for (int s = tid; s < 4096; s += TPB) {
        int ks = s >> 10, rest = s & 1023, ntg = rest >> 5, ln = rest & 31;
        int qq = ln & 3, gg = ln >> 2;
        int n = ntg * 8 + gg, r0 = ks * 16 + 2 * qq;
        uint2 b;
        b.x = pack_h2(W2[(r0)     * 256 + n], W2[(r0 + 1) * 256 + n]);
        b.y = pack_h2(W2[(r0 + 8) * 256 + n], W2[(r0 + 9) * 256 + n]);
        ((uint2*)(sm + OF_W2F))[s] = b;
    }
    // W1 [16][64]: frag (nt): n = nt*8 + g
    for (int s = tid; s < 256; s += TPB) {
        int nt = s >> 5, ln = s & 31;
        int qq = ln & 3, gg = ln >> 2;
        int n = nt * 8 + gg;
        uint2 b;
        b.x = pack_h2(W1[(2 * qq)     * 64 + n], W1[(2 * qq + 1) * 64 + n]);
        b.y = pack_h2(W1[(2 * qq + 8) * 64 + n], W1[(2 * qq + 9) * 64 + n]);
        ((uint2*)(sm + OF_W1F))[s] = b;
    }
    if (tid < 64)  sm[OF_B1 + tid] = b1[tid];
    if (tid < 256) sm[OF_B2 + tid] = b2[tid];

    const int ntiles = (n_edge + TILE - 1) / TILE;

    // ---- prologue: stage first tile into buffer 0 ----
    {
        const int t0 = blockIdx.x;
        if (t0 < ntiles) {
            const int base = t0 * TILE;
            const int rem  = n_edge - base;
            const int sr   = tid < rem ? tid : rem - 1;
            const float4* ep = (const float4*)(e_vw + (size_t)(base + sr) * 16);
            const float4* hp = (const float4*)(h_w + (size_t)(base + sr) * 16);
            uint32_t eh[8];
#pragma unroll
            for (int i = 0; i < 4; i++) {
                float4 v = __ldg(ep + i);
                eh[2 * i]     = pack_h2(v.x, v.y);
                eh[2 * i + 1] = pack_h2(v.z, v.w);
            }
            uint4* ed = (uint4*)((__half*)(sm + OF_E) + tid * 16);
            ed[0] = make_uint4(eh[0], eh[1], eh[2], eh[3]);
            ed[1] = make_uint4(eh[4], eh[5], eh[6], eh[7]);
            float4* hd = (float4*)(sm + OF_H + tid * 16);
#pragma unroll
            for (int i = 0; i < 4; i++) hd[i] = __ldg(hp + i);
        }
    }
    __syncthreads();

    int it = 0;
    for (int t = blockIdx.x; t < ntiles; t += gridDim.x, it++) {
        const int base = t * TILE;
        const int buf  = it & 1;
        const int nbuf = buf ^ 1;
        const uint32_t* E = (const uint32_t*)(sm + OF_E + buf * 2048); // e as half2
        const float*    H = sm + OF_H + buf * 4096;

        // ---- GEMM1 A-frags from current e buffer (rows warp*32+mt*16+{g,g+8}) ----
        uint32_t ea[2][4];
#pragma unroll
        for (int mt = 0; mt < 2; mt++) {
            int r0 = warp * 32 + mt * 16 + g;
            ea[mt][0] = E[r0 * 8 + q];            // (g,   2q..2q+1)
            ea[mt][1] = E[(r0 + 8) * 8 + q];      // (g+8, 2q..)
            ea[mt][2] = E[r0 * 8 + q + 4];        // (g,   2q+8..)
            ea[mt][3] = E[(r0 + 8) * 8 + q + 4];  // (g+8, 2q+8..)
        }

        // ---- issue next-tile global loads (hide under GEMM1/GEMM2) ----
        const int tn = t + gridDim.x;
        const bool has_next = tn < ntiles;
        float4 evn[4], hvn[4];
        if (has_next) {
            const int nb2 = tn * TILE;
            const int rem2 = n_edge - nb2;
            const int sr2  = tid < rem2 ? tid : rem2 - 1;
            const float4* ep = (const float4*)(e_vw + (size_t)(nb2 + sr2) * 16);
            const float4* hp = (const float4*)(h_w + (size_t)(nb2 + sr2) * 16);
#pragma unroll
            for (int i = 0; i < 4; i++) { evn[i] = __ldg(ep + i); hvn[i] = __ldg(hp + i); }
        }

        // ---- GEMM1: hid[32 x 64] per warp, one k-step ----
        float acc1[2][8][4];
#pragma unroll
        for (int mt = 0; mt < 2; mt++)
#pragma unroll
            for (int nt = 0; nt < 8; nt++)
#pragma unroll
                for (int r = 0; r < 4; r++) acc1[mt][nt][r] = 0.0f;
#pragma unroll
        for (int nt = 0; nt < 8; nt++) {
            uint2 b = ((const uint2*)(sm + OF_W1F))[nt * 32 + lane];
            MMA_F16(acc1[0][nt], ea[0], b.x, b.y);
            MMA_F16(acc1[1][nt], ea[1], b.x, b.y);
        }

        // ---- bias + relu + in-register repack to GEMM2 A-frags ----
        // GEMM1 D(nt): thread owns (g, nt*8+2q +0/1) and (g+8, same cols).
        // GEMM2 A-frag (ks = nt>>1): nt even -> a0/a1 (cols lo), nt odd -> a2/a3.
        uint32_t ha[2][4][4];
#pragma unroll
        for (int mt = 0; mt < 2; mt++)
#pragma unroll
            for (int nt = 0; nt < 8; nt++) {
                float2 bb = *(const float2*)(sm + OF_B1 + nt * 8 + 2 * q);
                float v0 = fmaxf(acc1[mt][nt][0] + bb.x, 0.0f);
                float v1 = fmaxf(acc1[mt][nt][1] + bb.y, 0.0f);
                float v2 = fmaxf(acc1[mt][nt][2] + bb.x, 0.0f);
                float v3 = fmaxf(acc1[mt][nt][3] + bb.y, 0.0f);
                int ks = nt >> 1, hi = (nt & 1) * 2;
                ha[mt][ks][hi]     = pack_h2(v0, v1);   // row g
                ha[mt][ks][hi + 1] = pack_h2(v2, v3);   // row g+8
            }

        // ---- h regs + nodes ----
        float hreg[2][2][4];
        int   node[2][2];
        bool  vld[2][2];
#pragma unroll
        for (int mt = 0; mt < 2; mt++)
#pragma unroll
            for (int rr = 0; rr < 2; rr++) {
                int row = warp * 32 + mt * 16 + g + rr * 8;
                float2 h0 = *(const float2*)(H + row * 16 + 2 * q);
                float2 h1 = *(const float2*)(H + row * 16 + 8 + 2 * q);
                hreg[mt][rr][0] = h0.x; hreg[mt][rr][1] = h0.y;
                hreg[mt][rr][2] = h1.x; hreg[mt][rr][3] = h1.y;
                int ge = base + row;
                vld[mt][rr]  = ge < n_edge;
                node[mt][rr] = vld[mt][rr] ? __ldg(index_v + ge) : 0;
            }

        // ---- store next-tile staging into the other buffer ----
        if (has_next) {
            uint32_t eh[8];
#pragma unroll
            for (int i = 0; i < 4; i++) {
                eh[2 * i]     = pack_h2(evn[i].x, evn[i].y);
                eh[2 * i + 1] = pack_h2(evn[i].z, evn[i].w);
            }
            uint4* ed = (uint4*)((__half*)(sm + OF_E + nbuf * 2048) + tid * 16);
            ed[0] = make_uint4(eh[0], eh[1], eh[2], eh[3]);
            ed[1] = make_uint4(eh[4], eh[5], eh[6], eh[7]);
            float4* hd = (float4*)(sm + OF_H + nbuf * 4096 + tid * 16);
#pragma unroll
            for (int i = 0; i < 4; i++) hd[i] = hvn[i];
        }

        // ---- GEMM2 + epilogue, 4 chunks of 64 cols ----
#pragma unroll
        for (int c = 0; c < 4; c++) {
            float acc[2][8][4];
#pragma unroll
            for (int mt = 0; mt < 2; mt++)
#pragma unroll
                for (int nt = 0; nt < 8; nt++)
#pragma unroll
                    for (int r = 0; r < 4; r++) acc[mt][nt][r] = 0.0f;
#pragma unroll
            for (int ks = 0; ks < 4; ks++)
#pragma unroll
                for (int nt = 0; nt < 8; nt++) {
                    uint2 b = ((const uint2*)(sm + OF_W2F))[(ks * 32 + c * 8 + nt) * 32 + lane];
                    MMA_F16(acc[0][nt], ha[0][ks], b.x, b.y);
                    MMA_F16(acc[1][nt], ha[1][ks], b.x, b.y);
                }
            float pacc[2][2][4];
#pragma unroll
            for (int mt = 0; mt < 2; mt++)
#pragma unroll
                for (int rr = 0; rr < 2; rr++)
#pragma unroll
                    for (int ml = 0; ml < 4; ml++) pacc[mt][rr][ml] = 0.0f;
#pragma unroll
            for (int mt = 0; mt < 2; mt++)
#pragma unroll
                for (int nt = 0; nt < 8; nt++) {
                    int ntg = c * 8 + nt;
                    float2 bb = *(const float2*)(sm + OF_B2 + ntg * 8 + 2 * q);
                    int hb = (nt & 1) * 2;
                    int ml = nt >> 1;
                    pacc[mt][0][ml] = fmaf(acc[mt][nt][0] + bb.x, hreg[mt][0][hb],     pacc[mt][0][ml]);
                    pacc[mt][0][ml] = fmaf(acc[mt][nt][1] + bb.y, hreg[mt][0][hb + 1], pacc[mt][0][ml]);
                    pacc[mt][1][ml] = fmaf(acc[mt][nt][2] + bb.x, hreg[mt][1][hb],     pacc[mt][1][ml]);
                    pacc[mt][1][ml] = fmaf(acc[mt][nt][3] + bb.y, hreg[mt][1][hb + 1], pacc[mt][1][ml]);
                }
#pragma unroll
            for (int mt = 0; mt < 2; mt++)
#pragma unroll
                for (int rr = 0; rr < 2; rr++) {
#pragma unroll
                    for (int ml = 0; ml < 4; ml++) {
                        float v = pacc[mt][rr][ml];
                        v += __shfl_xor_sync(0xFFFFFFFFu, v, 1);
                        v += __shfl_xor_sync(0xFFFFFFFFu, v, 2);
                        pacc[mt][rr][ml] = v;
                    }
                    if (q == 0 && vld[mt][rr]) {
                        red_add_v4(out + (size_t)node[mt][rr] * 16 + c * 4,
                                   pacc[mt][rr][0], pacc[mt][rr][1],
                                   pacc[mt][rr][2], pacc[mt][rr][3]);
                    }
                }
        }
        __syncthreads();  // next-buffer staging visible; current buffer reads done
    }
}

// ---------------- launch ----------------
extern "C" void kernel_launch(void* const* d_in, const int* in_sizes, int n_in,
                              void* d_out, int out_size) {
    const int*   index_v = nullptr;
    const float* h_w = nullptr;
    const float* e_vw = nullptr;
    const float* W1 = nullptr;
    const float* b1 = nullptr;
    const float* W2 = nullptr;
    const float* b2 = nullptr;

    int big_idx[8]; long long big_sz[8]; int nb = 0;
    for (int i = 0; i < n_in; i++) {
        long long s = in_sizes[i];
        if (s == 1024)       W1 = (const float*)d_in[i];
        else if (s == 64)    b1 = (const float*)d_in[i];
        else if (s == 16384) W2 = (const float*)d_in[i];
        else if (s == 256)   b2 = (const float*)d_in[i];
        else if (s > 100000 && nb < 8) { big_idx[nb] = i; big_sz[nb] = s; nb++; }
    }
    long long min_sz = big_sz[0]; int min_pos = 0;
    for (int i = 1; i < nb; i++)
        if (big_sz[i] < min_sz) { min_sz = big_sz[i]; min_pos = i; }
    index_v = (const int*)d_in[big_idx[min_pos]];
    int n_edge = (int)min_sz;
    bool got_h = false;
    for (int i = 0; i < nb; i++) {
        if (i == min_pos) continue;
        if (!got_h) { h_w = (const float*)d_in[big_idx[i]]; got_h = true; }
        else        { e_vw = (const float*)d_in[big_idx[i]]; }
    }

    float* out = (float*)d_out;
    cudaMemsetAsync(out, 0, (size_t)out_size * sizeof(float));

    static bool attr_set = false;
    if (!attr_set) {
        cudaFuncSetAttribute(msg_mma_kernel,
                             cudaFuncAttributeMaxDynamicSharedMemorySize,
                             SMEM_FLOATS * (int)sizeof(float));
        attr_set = true;
    }
    int ntiles = (n_edge + TILE - 1) / TILE;
    int grid = ntiles < 152 ? ntiles : 152;
    msg_mma_kernel<<<grid, TPB, SMEM_FLOATS * sizeof(float)>>>(
        index_v, h_w, e_vw, W1, b1, W2, b2, out, n_edge);
}